// round 2
// baseline (speedup 1.0000x reference)
#include <cuda_runtime.h>
#include <cuda_bf16.h>

#define NN 50000
#define EE 600000
#define DD 128
#define GG 256
#define OO 10
#define LL 5
#define BN_EPS 1e-5f

// Scratch (static device globals — no runtime allocation).
// NOTE: never take their address in HOST code (resolves to host shadow via ATS
// on GB300 — silent corruption). Device code only.
__device__ float g_xcur[NN * DD];
__device__ float g_aggr[NN * DD];
__device__ float g_h1[NN * DD];
__device__ float g_pooled[(LL + 1) * GG * DD];
__device__ float g_counts[GG];

// ---------------------------------------------------------------------------
__global__ void k_zero_meta() {
    int total = (LL + 1) * GG * DD + GG;
    for (int i = blockIdx.x * blockDim.x + threadIdx.x; i < total; i += gridDim.x * blockDim.x) {
        if (i < (LL + 1) * GG * DD) g_pooled[i] = 0.f;
        else g_counts[i - (LL + 1) * GG * DD] = 0.f;
    }
}

__global__ void k_zero_aggr() {
    float4* p = reinterpret_cast<float4*>(g_aggr);
    int total = NN * DD / 4;
    for (int i = blockIdx.x * blockDim.x + threadIdx.x; i < total; i += gridDim.x * blockDim.x) {
        p[i] = make_float4(0.f, 0.f, 0.f, 0.f);
    }
}

__global__ void k_counts(const int* __restrict__ batch) {
    int n = blockIdx.x * blockDim.x + threadIdx.x;
    if (n < NN) atomicAdd(&g_counts[batch[n]], 1.0f);
}

// copy x -> xcur, pool layer-0 output into slot 0
__global__ void k_copy_pool0(const float* __restrict__ x, const int* __restrict__ batch) {
    long long t = (long long)blockIdx.x * blockDim.x + threadIdx.x;
    int n = (int)(t >> 5);
    int lane = (int)(t & 31);
    if (n >= NN) return;
    int g = batch[n];
    float4 v = reinterpret_cast<const float4*>(x)[(long long)n * 32 + lane];
    reinterpret_cast<float4*>(g_xcur)[(long long)n * 32 + lane] = v;
    float* pd = &g_pooled[g * DD + lane * 4];
    atomicAdd(pd + 0, v.x);
    atomicAdd(pd + 1, v.y);
    atomicAdd(pd + 2, v.z);
    atomicAdd(pd + 3, v.w);
}

// ---------------------------------------------------------------------------
// Edge kernel: one warp per edge. msg = relu(x[src] + sum_f emb[f][attr_f]); atomicAdd to aggr[dst]
__global__ void k_edge(const int* __restrict__ edge_index,
                       const int* __restrict__ edge_attr,
                       const float* __restrict__ bond_layer /* [3][8][D] */) {
    long long t = (long long)blockIdx.x * blockDim.x + threadIdx.x;
    int e = (int)(t >> 5);
    int lane = (int)(t & 31);
    if (e >= EE) return;
    int src = edge_index[e];
    int dst = edge_index[EE + e];
    int a0 = edge_attr[e * 3 + 0];
    int a1 = edge_attr[e * 3 + 1];
    int a2 = edge_attr[e * 3 + 2];
    const float4* b4 = reinterpret_cast<const float4*>(bond_layer);
    float4 e0 = b4[(0 * 8 + a0) * 32 + lane];
    float4 e1 = b4[(1 * 8 + a1) * 32 + lane];
    float4 e2 = b4[(2 * 8 + a2) * 32 + lane];
    float4 xv = reinterpret_cast<const float4*>(g_xcur)[(long long)src * 32 + lane];
    float m0 = fmaxf(xv.x + e0.x + e1.x + e2.x, 0.f);
    float m1 = fmaxf(xv.y + e0.y + e1.y + e2.y, 0.f);
    float m2 = fmaxf(xv.z + e0.z + e1.z + e2.z, 0.f);
    float m3 = fmaxf(xv.w + e0.w + e1.w + e2.w, 0.f);
    float* ad = &g_aggr[(long long)dst * DD + lane * 4];
    atomicAdd(ad + 0, m0);
    atomicAdd(ad + 1, m1);
    atomicAdd(ad + 2, m2);
    atomicAdd(ad + 3, m3);
}

// ---------------------------------------------------------------------------
// Fused GEMM + bias + BN + relu. Scratch arrays referenced via device symbols.
// MODE 0: in = g_xcur + g_aggr, out = g_h1, no pooling
// MODE 1: in = g_h1,            out = g_xcur, pool into g_pooled slot `pool_slot`
template <int MODE>
__global__ void __launch_bounds__(256, 2)
k_gemm(const float* __restrict__ W, const float* __restrict__ bias,
       const float* __restrict__ gamma, const float* __restrict__ beta,
       const float* __restrict__ mean, const float* __restrict__ var,
       const int* __restrict__ batch, int pool_slot) {
    extern __shared__ float smem[];
    float* Bs = smem;              // [128][128]
    float* As = smem + DD * DD;    // [64][128]

    const int tid = threadIdx.x;
    const int m0 = blockIdx.x * 64;

    // Load W tile
    {
        const float4* Wg = reinterpret_cast<const float4*>(W);
        float4* Bs4 = reinterpret_cast<float4*>(Bs);
        #pragma unroll
        for (int i = 0; i < (DD * DD / 4) / 256; i++) {
            Bs4[tid + i * 256] = Wg[tid + i * 256];
        }
    }
    // Load A tile
    {
        float4* As4 = reinterpret_cast<float4*>(As);
        const float4* Ag = reinterpret_cast<const float4*>(MODE == 0 ? g_xcur : g_h1);
        const float4* A2g = reinterpret_cast<const float4*>(g_aggr);
        #pragma unroll
        for (int i = 0; i < (64 * DD / 4) / 256; i++) {
            int idx = tid + i * 256;
            int row = idx >> 5;
            int c4 = idx & 31;
            int m = m0 + row;
            float4 v = make_float4(0.f, 0.f, 0.f, 0.f);
            if (m < NN) {
                v = Ag[(long long)m * 32 + c4];
                if (MODE == 0) {
                    float4 w = A2g[(long long)m * 32 + c4];
                    v.x += w.x; v.y += w.y; v.z += w.z; v.w += w.w;
                }
            }
            As4[idx] = v;
        }
    }
    __syncthreads();

    const int rowg = tid >> 5;
    const int lane = tid & 31;
    float acc[8][4];
    #pragma unroll
    for (int j = 0; j < 8; j++)
        #pragma unroll
        for (int c = 0; c < 4; c++) acc[j][c] = 0.f;

    const float4* As4 = reinterpret_cast<const float4*>(As);
    const float4* Bs4 = reinterpret_cast<const float4*>(Bs);

    #pragma unroll 4
    for (int kk = 0; kk < 32; kk++) {
        float4 b0 = Bs4[(4 * kk + 0) * 32 + lane];
        float4 b1 = Bs4[(4 * kk + 1) * 32 + lane];
        float4 b2 = Bs4[(4 * kk + 2) * 32 + lane];
        float4 b3 = Bs4[(4 * kk + 3) * 32 + lane];
        #pragma unroll
        for (int j = 0; j < 8; j++) {
            float4 a = As4[(rowg * 8 + j) * 32 + kk];
            acc[j][0] += a.x * b0.x + a.y * b1.x + a.z * b2.x + a.w * b3.x;
            acc[j][1] += a.x * b0.y + a.y * b1.y + a.z * b2.y + a.w * b3.y;
            acc[j][2] += a.x * b0.z + a.y * b1.z + a.z * b2.z + a.w * b3.z;
            acc[j][3] += a.x * b0.w + a.y * b1.w + a.z * b2.w + a.w * b3.w;
        }
    }

    const int c0 = lane * 4;
    float4 bi = *reinterpret_cast<const float4*>(bias + c0);
    float4 ga = *reinterpret_cast<const float4*>(gamma + c0);
    float4 be = *reinterpret_cast<const float4*>(beta + c0);
    float4 me = *reinterpret_cast<const float4*>(mean + c0);
    float4 va = *reinterpret_cast<const float4*>(var + c0);
    float4 sc, sh;
    sc.x = ga.x * rsqrtf(va.x + BN_EPS); sh.x = be.x - me.x * sc.x;
    sc.y = ga.y * rsqrtf(va.y + BN_EPS); sh.y = be.y - me.y * sc.y;
    sc.z = ga.z * rsqrtf(va.z + BN_EPS); sh.z = be.z - me.z * sc.z;
    sc.w = ga.w * rsqrtf(va.w + BN_EPS); sh.w = be.w - me.w * sc.w;

    float* Cout = (MODE == 0) ? g_h1 : g_xcur;

    #pragma unroll
    for (int j = 0; j < 8; j++) {
        int m = m0 + rowg * 8 + j;
        if (m >= NN) break;
        float4 r;
        r.x = fmaxf((acc[j][0] + bi.x) * sc.x + sh.x, 0.f);
        r.y = fmaxf((acc[j][1] + bi.y) * sc.y + sh.y, 0.f);
        r.z = fmaxf((acc[j][2] + bi.z) * sc.z + sh.z, 0.f);
        r.w = fmaxf((acc[j][3] + bi.w) * sc.w + sh.w, 0.f);
        reinterpret_cast<float4*>(Cout)[(long long)m * 32 + lane] = r;
        if (MODE == 1) {
            int g = batch[m];
            float* pd = &g_pooled[pool_slot * GG * DD + g * DD + c0];
            atomicAdd(pd + 0, r.x);
            atomicAdd(pd + 1, r.y);
            atomicAdd(pd + 2, r.z);
            atomicAdd(pd + 3, r.w);
        }
    }
}

// ---------------------------------------------------------------------------
__global__ void k_head(const float* __restrict__ fc_w, const float* __restrict__ fc_b,
                       float* __restrict__ out) {
    __shared__ float sp[(LL + 1) * DD];
    int g = blockIdx.x;
    float inv = 1.0f / fmaxf(g_counts[g], 1.0f);
    for (int i = threadIdx.x; i < (LL + 1) * DD; i += blockDim.x) {
        int l = i >> 7;
        int d = i & 127;
        sp[i] = g_pooled[l * GG * DD + g * DD + d] * inv;
    }
    __syncthreads();
    int o = threadIdx.x;
    if (o < OO) {
        float s = 0.f;
        #pragma unroll
        for (int l = 0; l < LL + 1; l++) {
            float partial = 0.f;
            for (int d = 0; d < DD; d++) {
                partial += sp[l * DD + d] * fc_w[(l * DD + d) * OO + o];
            }
            s += partial + fc_b[l * OO + o];
        }
        out[g * OO + o] = s;
    }
}

// ---------------------------------------------------------------------------
extern "C" void kernel_launch(void* const* d_in, const int* in_sizes, int n_in,
                              void* d_out, int out_size) {
    const float* x          = (const float*)d_in[0];
    const int*   edge_index = (const int*)d_in[1];
    const int*   edge_attr  = (const int*)d_in[2];
    const int*   batch      = (const int*)d_in[3];
    const float* bond_emb   = (const float*)d_in[4];
    const float* conv_w1    = (const float*)d_in[5];
    const float* conv_b1    = (const float*)d_in[6];
    const float* cbn_g      = (const float*)d_in[7];
    const float* cbn_b      = (const float*)d_in[8];
    const float* cbn_m      = (const float*)d_in[9];
    const float* cbn_v      = (const float*)d_in[10];
    const float* conv_w2    = (const float*)d_in[11];
    const float* conv_b2    = (const float*)d_in[12];
    const float* bn_g       = (const float*)d_in[13];
    const float* bn_b       = (const float*)d_in[14];
    const float* bn_m       = (const float*)d_in[15];
    const float* bn_v       = (const float*)d_in[16];
    const float* fc_w       = (const float*)d_in[17];
    const float* fc_b       = (const float*)d_in[18];
    float* out = (float*)d_out;

    const int smem_bytes = (DD * DD + 64 * DD) * sizeof(float);  // 96 KB
    static bool attr_done = false;
    if (!attr_done) {
        cudaFuncSetAttribute(k_gemm<0>, cudaFuncAttributeMaxDynamicSharedMemorySize, smem_bytes);
        cudaFuncSetAttribute(k_gemm<1>, cudaFuncAttributeMaxDynamicSharedMemorySize, smem_bytes);
        attr_done = true;
    }

    k_zero_meta<<<256, 256>>>();
    k_counts<<<(NN + 255) / 256, 256>>>(batch);
    {
        long long tot = (long long)NN * 32;
        k_copy_pool0<<<(int)((tot + 255) / 256), 256>>>(x, batch);
    }

    const int gemm_grid = (NN + 63) / 64;

    for (int i = 0; i < LL; i++) {
        k_zero_aggr<<<2048, 256>>>();
        {
            long long tot = (long long)EE * 32;
            k_edge<<<(int)((tot + 255) / 256), 256>>>(
                edge_index, edge_attr, bond_emb + (long long)i * 3 * 8 * DD);
        }
        k_gemm<0><<<gemm_grid, 256, smem_bytes>>>(
            conv_w1 + (long long)i * DD * DD, conv_b1 + i * DD,
            cbn_g + i * DD, cbn_b + i * DD, cbn_m + i * DD, cbn_v + i * DD,
            batch, 0);
        k_gemm<1><<<gemm_grid, 256, smem_bytes>>>(
            conv_w2 + (long long)i * DD * DD, conv_b2 + i * DD,
            bn_g + i * DD, bn_b + i * DD, bn_m + i * DD, bn_v + i * DD,
            batch, i + 1);
    }

    k_head<<<GG, 128>>>(fc_w, fc_b, out);
    (void)in_sizes; (void)n_in; (void)out_size;
}

// round 4
// speedup vs baseline: 1.7782x; 1.7782x over previous
#include <cuda_runtime.h>
#include <cuda_bf16.h>
#include <cstdint>

#define NN 50000
#define EE 600000
#define DD 128
#define GG 256
#define OO 10
#define LL 5
#define BN_EPS 1e-5f

// Scratch (static device globals — no runtime allocation).
// NOTE: never reference these symbols in HOST code (ATS resolves the host
// shadow silently on GB300). Device code only.
__device__ float g_xcur[NN * DD];
__device__ float g_aggr[NN * DD];
__device__ float g_h1[NN * DD];
__device__ float g_pooled[(LL + 1) * GG * DD];
__device__ float g_counts[GG];

// ---------------------------------------------------------------------------
__device__ __forceinline__ uint32_t f2tf32(float f) {
    uint32_t r;
    asm("cvt.rna.tf32.f32 %0, %1;" : "=r"(r) : "f"(f));
    return r;
}

__device__ __forceinline__ void mma_tf32(float* c, const uint32_t* a, uint32_t b0, uint32_t b1) {
    asm volatile(
        "mma.sync.aligned.m16n8k8.row.col.f32.tf32.tf32.f32 "
        "{%0,%1,%2,%3}, {%4,%5,%6,%7}, {%8,%9}, {%0,%1,%2,%3};"
        : "+f"(c[0]), "+f"(c[1]), "+f"(c[2]), "+f"(c[3])
        : "r"(a[0]), "r"(a[1]), "r"(a[2]), "r"(a[3]), "r"(b0), "r"(b1));
}

__device__ __forceinline__ void red_v4(float* addr, float x, float y, float z, float w) {
    asm volatile("red.global.add.v4.f32 [%0], {%1,%2,%3,%4};"
                 :: "l"(addr), "f"(x), "f"(y), "f"(z), "f"(w) : "memory");
}

__device__ __forceinline__ void red_v2(float* addr, float x, float y) {
    asm volatile("red.global.add.v2.f32 [%0], {%1,%2};"
                 :: "l"(addr), "f"(x), "f"(y) : "memory");
}

// ---------------------------------------------------------------------------
__global__ void k_zero_meta() {
    int total = (LL + 1) * GG * DD + GG;
    for (int i = blockIdx.x * blockDim.x + threadIdx.x; i < total; i += gridDim.x * blockDim.x) {
        if (i < (LL + 1) * GG * DD) g_pooled[i] = 0.f;
        else g_counts[i - (LL + 1) * GG * DD] = 0.f;
    }
}

__global__ void k_zero_aggr() {
    float4* p = reinterpret_cast<float4*>(g_aggr);
    int total = NN * DD / 4;
    for (int i = blockIdx.x * blockDim.x + threadIdx.x; i < total; i += gridDim.x * blockDim.x) {
        p[i] = make_float4(0.f, 0.f, 0.f, 0.f);
    }
}

__global__ void k_counts(const int* __restrict__ batch) {
    int n = blockIdx.x * blockDim.x + threadIdx.x;
    if (n < NN) atomicAdd(&g_counts[batch[n]], 1.0f);
}

__global__ void k_copy_pool0(const float* __restrict__ x, const int* __restrict__ batch) {
    long long t = (long long)blockIdx.x * blockDim.x + threadIdx.x;
    int n = (int)(t >> 5);
    int lane = (int)(t & 31);
    if (n >= NN) return;
    int g = batch[n];
    float4 v = reinterpret_cast<const float4*>(x)[(long long)n * 32 + lane];
    reinterpret_cast<float4*>(g_xcur)[(long long)n * 32 + lane] = v;
    red_v4(&g_pooled[g * DD + lane * 4], v.x, v.y, v.z, v.w);
}

// ---------------------------------------------------------------------------
// Edge kernel: one warp per edge; vector reduction to aggr[dst].
__global__ void k_edge(const int* __restrict__ edge_index,
                       const int* __restrict__ edge_attr,
                       const float* __restrict__ bond_layer /* [3][8][D] */) {
    long long t = (long long)blockIdx.x * blockDim.x + threadIdx.x;
    int e = (int)(t >> 5);
    int lane = (int)(t & 31);
    if (e >= EE) return;
    int src = edge_index[e];
    int dst = edge_index[EE + e];
    int a0 = edge_attr[e * 3 + 0];
    int a1 = edge_attr[e * 3 + 1];
    int a2 = edge_attr[e * 3 + 2];
    const float4* b4 = reinterpret_cast<const float4*>(bond_layer);
    float4 e0 = b4[(0 * 8 + a0) * 32 + lane];
    float4 e1 = b4[(1 * 8 + a1) * 32 + lane];
    float4 e2 = b4[(2 * 8 + a2) * 32 + lane];
    float4 xv = reinterpret_cast<const float4*>(g_xcur)[(long long)src * 32 + lane];
    float m0 = fmaxf(xv.x + e0.x + e1.x + e2.x, 0.f);
    float m1 = fmaxf(xv.y + e0.y + e1.y + e2.y, 0.f);
    float m2 = fmaxf(xv.z + e0.z + e1.z + e2.z, 0.f);
    float m3 = fmaxf(xv.w + e0.w + e1.w + e2.w, 0.f);
    red_v4(&g_aggr[(long long)dst * DD + lane * 4], m0, m1, m2, m3);
}

// ---------------------------------------------------------------------------
// Tensor-core GEMM (tf32, W split hi/lo for accuracy) + bias + BN + relu.
// MODE 0: in = g_xcur + g_aggr, out = g_h1
// MODE 1: in = g_h1,            out = g_xcur, pool into g_pooled[pool_slot]
// Block: 256 threads (8 warps), BM=128 rows, full N=K=128.
// Warp w: wm = w&3 (row group of 32), wn = w>>2 (col group of 64).
#define SA_STRIDE 132
#define SW_STRIDE 136

template <int MODE>
__global__ void __launch_bounds__(256, 1)
k_gemm_tc(const float* __restrict__ W, const float* __restrict__ bias,
          const float* __restrict__ gamma, const float* __restrict__ beta,
          const float* __restrict__ mean, const float* __restrict__ var,
          const int* __restrict__ batch, int pool_slot) {
    extern __shared__ uint32_t smem_u[];
    uint32_t* sA  = smem_u;                         // [128][132]
    uint32_t* sWh = sA + DD * SA_STRIDE;            // [128][136]
    uint32_t* sWl = sWh + DD * SW_STRIDE;           // [128][136]

    const int tid = threadIdx.x;
    const int m0 = blockIdx.x * 128;

    // ---- Load A tile (+aggr for MODE 0), convert to tf32 ----
    {
        const float4* Ag  = reinterpret_cast<const float4*>(MODE == 0 ? g_xcur : g_h1);
        const float4* A2g = reinterpret_cast<const float4*>(g_aggr);
        #pragma unroll
        for (int i = 0; i < 16; i++) {
            int idx = tid + i * 256;        // 0..4095
            int row = idx >> 5;             // 0..127
            int c4  = idx & 31;
            int m = m0 + row;
            float4 v = make_float4(0.f, 0.f, 0.f, 0.f);
            if (m < NN) {
                v = Ag[(long long)m * 32 + c4];
                if (MODE == 0) {
                    float4 w = A2g[(long long)m * 32 + c4];
                    v.x += w.x; v.y += w.y; v.z += w.z; v.w += w.w;
                }
            }
            uint4 tv;
            tv.x = f2tf32(v.x); tv.y = f2tf32(v.y); tv.z = f2tf32(v.z); tv.w = f2tf32(v.w);
            *reinterpret_cast<uint4*>(&sA[row * SA_STRIDE + c4 * 4]) = tv;
        }
    }
    // ---- Load W tile, split into tf32 hi + lo ----
    {
        const float4* Wg = reinterpret_cast<const float4*>(W);
        #pragma unroll
        for (int i = 0; i < 16; i++) {
            int idx = tid + i * 256;
            int row = idx >> 5;
            int c4  = idx & 31;
            float4 w = Wg[row * 32 + c4];
            uint4 hi, lo;
            hi.x = f2tf32(w.x); lo.x = f2tf32(w.x - __uint_as_float(hi.x));
            hi.y = f2tf32(w.y); lo.y = f2tf32(w.y - __uint_as_float(hi.y));
            hi.z = f2tf32(w.z); lo.z = f2tf32(w.z - __uint_as_float(hi.z));
            hi.w = f2tf32(w.w); lo.w = f2tf32(w.w - __uint_as_float(hi.w));
            *reinterpret_cast<uint4*>(&sWh[row * SW_STRIDE + c4 * 4]) = hi;
            *reinterpret_cast<uint4*>(&sWl[row * SW_STRIDE + c4 * 4]) = lo;
        }
    }
    __syncthreads();

    const int w    = tid >> 5;
    const int lane = tid & 31;
    const int wm   = w & 3;       // row group: rows wm*32 .. wm*32+31
    const int wn   = w >> 2;      // col group: cols wn*64 .. wn*64+63
    const int gid  = lane >> 2;   // 0..7
    const int tig  = lane & 3;    // 0..3

    float acc[2][8][4];
    #pragma unroll
    for (int mi = 0; mi < 2; mi++)
        #pragma unroll
        for (int ni = 0; ni < 8; ni++)
            #pragma unroll
            for (int r = 0; r < 4; r++) acc[mi][ni][r] = 0.f;

    const uint32_t* aRow0  = sA + (wm * 32 + 0 * 16 + gid) * SA_STRIDE;
    const uint32_t* aRow0b = aRow0 + 8 * SA_STRIDE;
    const uint32_t* aRow1  = sA + (wm * 32 + 1 * 16 + gid) * SA_STRIDE;
    const uint32_t* aRow1b = aRow1 + 8 * SA_STRIDE;
    const int colbase = wn * 64 + gid;

    for (int kk = 0; kk < 16; kk++) {
        int k0 = kk * 8 + tig;
        uint32_t a0[4], a1[4];
        a0[0] = aRow0[k0];  a0[1] = aRow0b[k0];  a0[2] = aRow0[k0 + 4];  a0[3] = aRow0b[k0 + 4];
        a1[0] = aRow1[k0];  a1[1] = aRow1b[k0];  a1[2] = aRow1[k0 + 4];  a1[3] = aRow1b[k0 + 4];
        int kb0 = k0 * SW_STRIDE;
        int kb1 = (k0 + 4) * SW_STRIDE;
        #pragma unroll
        for (int ni = 0; ni < 8; ni++) {
            int c = colbase + ni * 8;
            uint32_t bh0 = sWh[kb0 + c], bh1 = sWh[kb1 + c];
            uint32_t bl0 = sWl[kb0 + c], bl1 = sWl[kb1 + c];
            mma_tf32(acc[0][ni], a0, bh0, bh1);
            mma_tf32(acc[0][ni], a0, bl0, bl1);
            mma_tf32(acc[1][ni], a1, bh0, bh1);
            mma_tf32(acc[1][ni], a1, bl0, bl1);
        }
    }

    // ---- Epilogue: bias + BN + relu, store, optional pooling ----
    float* Cout = (MODE == 0) ? g_h1 : g_xcur;
    #pragma unroll
    for (int ni = 0; ni < 8; ni++) {
        int c = wn * 64 + ni * 8 + tig * 2;
        float2 bi = *reinterpret_cast<const float2*>(bias + c);
        float2 ga = *reinterpret_cast<const float2*>(gamma + c);
        float2 be = *reinterpret_cast<const float2*>(beta + c);
        float2 me = *reinterpret_cast<const float2*>(mean + c);
        float2 va = *reinterpret_cast<const float2*>(var + c);
        float scx = ga.x * rsqrtf(va.x + BN_EPS);
        float scy = ga.y * rsqrtf(va.y + BN_EPS);
        float shx = be.x - me.x * scx;
        float shy = be.y - me.y * scy;
        #pragma unroll
        for (int mi = 0; mi < 2; mi++) {
            #pragma unroll
            for (int h = 0; h < 2; h++) {
                int row = m0 + wm * 32 + mi * 16 + gid + h * 8;
                if (row < NN) {
                    float v0 = acc[mi][ni][h * 2 + 0];
                    float v1 = acc[mi][ni][h * 2 + 1];
                    float r0 = fmaxf((v0 + bi.x) * scx + shx, 0.f);
                    float r1 = fmaxf((v1 + bi.y) * scy + shy, 0.f);
                    *reinterpret_cast<float2*>(&Cout[(long long)row * DD + c]) = make_float2(r0, r1);
                    if (MODE == 1) {
                        int g = batch[row];
                        red_v2(&g_pooled[pool_slot * GG * DD + g * DD + c], r0, r1);
                    }
                }
            }
        }
    }
}

// ---------------------------------------------------------------------------
__global__ void k_head(const float* __restrict__ fc_w, const float* __restrict__ fc_b,
                       float* __restrict__ out) {
    __shared__ float sp[(LL + 1) * DD];
    int g = blockIdx.x;
    float inv = 1.0f / fmaxf(g_counts[g], 1.0f);
    for (int i = threadIdx.x; i < (LL + 1) * DD; i += blockDim.x) {
        int l = i >> 7;
        int d = i & 127;
        sp[i] = g_pooled[l * GG * DD + g * DD + d] * inv;
    }
    __syncthreads();
    int o = threadIdx.x;
    if (o < OO) {
        float s = 0.f;
        #pragma unroll
        for (int l = 0; l < LL + 1; l++) {
            float partial = 0.f;
            for (int d = 0; d < DD; d++) {
                partial += sp[l * DD + d] * fc_w[(l * DD + d) * OO + o];
            }
            s += partial + fc_b[l * OO + o];
        }
        out[g * OO + o] = s;
    }
}

// ---------------------------------------------------------------------------
extern "C" void kernel_launch(void* const* d_in, const int* in_sizes, int n_in,
                              void* d_out, int out_size) {
    const float* x          = (const float*)d_in[0];
    const int*   edge_index = (const int*)d_in[1];
    const int*   edge_attr  = (const int*)d_in[2];
    const int*   batch      = (const int*)d_in[3];
    const float* bond_emb   = (const float*)d_in[4];
    const float* conv_w1    = (const float*)d_in[5];
    const float* conv_b1    = (const float*)d_in[6];
    const float* cbn_g      = (const float*)d_in[7];
    const float* cbn_b      = (const float*)d_in[8];
    const float* cbn_m      = (const float*)d_in[9];
    const float* cbn_v      = (const float*)d_in[10];
    const float* conv_w2    = (const float*)d_in[11];
    const float* conv_b2    = (const float*)d_in[12];
    const float* bn_g       = (const float*)d_in[13];
    const float* bn_b       = (const float*)d_in[14];
    const float* bn_m       = (const float*)d_in[15];
    const float* bn_v       = (const float*)d_in[16];
    const float* fc_w       = (const float*)d_in[17];
    const float* fc_b       = (const float*)d_in[18];
    float* out = (float*)d_out;

    const int smem_bytes = (DD * SA_STRIDE + 2 * DD * SW_STRIDE) * sizeof(uint32_t); // ~202 KB
    static bool attr_done = false;
    if (!attr_done) {
        cudaFuncSetAttribute(k_gemm_tc<0>, cudaFuncAttributeMaxDynamicSharedMemorySize, smem_bytes);
        cudaFuncSetAttribute(k_gemm_tc<1>, cudaFuncAttributeMaxDynamicSharedMemorySize, smem_bytes);
        attr_done = true;
    }

    k_zero_meta<<<256, 256>>>();
    k_counts<<<(NN + 255) / 256, 256>>>(batch);
    {
        long long tot = (long long)NN * 32;
        k_copy_pool0<<<(int)((tot + 255) / 256), 256>>>(x, batch);
    }

    const int gemm_grid = (NN + 127) / 128;

    for (int i = 0; i < LL; i++) {
        k_zero_aggr<<<2048, 256>>>();
        {
            long long tot = (long long)EE * 32;
            k_edge<<<(int)((tot + 255) / 256), 256>>>(
                edge_index, edge_attr, bond_emb + (long long)i * 3 * 8 * DD);
        }
        k_gemm_tc<0><<<gemm_grid, 256, smem_bytes>>>(
            conv_w1 + (long long)i * DD * DD, conv_b1 + i * DD,
            cbn_g + i * DD, cbn_b + i * DD, cbn_m + i * DD, cbn_v + i * DD,
            batch, 0);
        k_gemm_tc<1><<<gemm_grid, 256, smem_bytes>>>(
            conv_w2 + (long long)i * DD * DD, conv_b2 + i * DD,
            bn_g + i * DD, bn_b + i * DD, bn_m + i * DD, bn_v + i * DD,
            batch, i + 1);
    }

    k_head<<<GG, 128>>>(fc_w, fc_b, out);
    (void)in_sizes; (void)n_in; (void)out_size;
}

// round 6
// speedup vs baseline: 2.6061x; 1.4655x over previous
#include <cuda_runtime.h>
#include <cuda_bf16.h>
#include <cstdint>

#define NN 50000
#define EE 600000
#define DD 128
#define GG 256
#define OO 10
#define LL 5
#define BN_EPS 1e-5f

// Scratch (static device globals — no runtime allocation).
// NOTE: never reference these symbols in HOST code (ATS resolves the host
// shadow silently on GB300). Device code only.
__device__ float g_xcur[NN * DD];
__device__ float g_aggr[NN * DD];      // holds x + aggregated messages (GEMM1 input)
__device__ float g_h1[NN * DD];
__device__ float g_pooled[(LL + 1) * GG * DD];
__device__ float g_counts[GG];

// CSR scratch
__device__ int g_deg[NN];
__device__ int g_off[NN + 1];
__device__ int g_epos[NN];
__device__ int g_bsum[128];
__device__ int g_esrc[EE];
__device__ int g_eattr[EE];   // packed a0 | a1<<3 | a2<<6

#define SCAN_B 512
#define SCAN_NBLK ((NN + SCAN_B - 1) / SCAN_B)   // 98

// ---------------------------------------------------------------------------
__device__ __forceinline__ uint32_t f2tf32(float f) {
    uint32_t r;
    asm("cvt.rna.tf32.f32 %0, %1;" : "=r"(r) : "f"(f));
    return r;
}

__device__ __forceinline__ void mma_tf32(float* c, const uint32_t* a, uint32_t b0, uint32_t b1) {
    asm volatile(
        "mma.sync.aligned.m16n8k8.row.col.f32.tf32.tf32.f32 "
        "{%0,%1,%2,%3}, {%4,%5,%6,%7}, {%8,%9}, {%0,%1,%2,%3};"
        : "+f"(c[0]), "+f"(c[1]), "+f"(c[2]), "+f"(c[3])
        : "r"(a[0]), "r"(a[1]), "r"(a[2]), "r"(a[3]), "r"(b0), "r"(b1));
}

__device__ __forceinline__ void red_v4(float* addr, float x, float y, float z, float w) {
    asm volatile("red.global.add.v4.f32 [%0], {%1,%2,%3,%4};"
                 :: "l"(addr), "f"(x), "f"(y), "f"(z), "f"(w) : "memory");
}

__device__ __forceinline__ void red_v2(float* addr, float x, float y) {
    asm volatile("red.global.add.v2.f32 [%0], {%1,%2};"
                 :: "l"(addr), "f"(x), "f"(y) : "memory");
}

// ---------------------------------------------------------------------------
__global__ void k_zero_meta() {
    int tot1 = (LL + 1) * GG * DD;
    int total = tot1 + GG + NN;
    for (int i = blockIdx.x * blockDim.x + threadIdx.x; i < total; i += gridDim.x * blockDim.x) {
        if (i < tot1) g_pooled[i] = 0.f;
        else if (i < tot1 + GG) g_counts[i - tot1] = 0.f;
        else g_deg[i - tot1 - GG] = 0;
    }
}

__global__ void k_counts(const int* __restrict__ batch) {
    int n = blockIdx.x * blockDim.x + threadIdx.x;
    if (n < NN) atomicAdd(&g_counts[batch[n]], 1.0f);
}

__global__ void k_copy_pool0(const float* __restrict__ x, const int* __restrict__ batch) {
    long long t = (long long)blockIdx.x * blockDim.x + threadIdx.x;
    int n = (int)(t >> 5);
    int lane = (int)(t & 31);
    if (n >= NN) return;
    int g = batch[n];
    float4 v = reinterpret_cast<const float4*>(x)[(long long)n * 32 + lane];
    reinterpret_cast<float4*>(g_xcur)[(long long)n * 32 + lane] = v;
    red_v4(&g_pooled[g * DD + lane * 4], v.x, v.y, v.z, v.w);
}

// ---------------------------------------------------------------------------
// CSR build
__global__ void k_hist(const int* __restrict__ edge_index) {
    int e = blockIdx.x * blockDim.x + threadIdx.x;
    if (e < EE) atomicAdd(&g_deg[edge_index[EE + e]], 1);
}

__global__ void k_scan_part() {
    __shared__ int s[SCAN_B];
    int t = threadIdx.x;
    int idx = blockIdx.x * SCAN_B + t;
    int val = (idx < NN) ? g_deg[idx] : 0;
    s[t] = val;
    __syncthreads();
    #pragma unroll
    for (int d = 1; d < SCAN_B; d <<= 1) {
        int v = (t >= d) ? s[t - d] : 0;
        __syncthreads();
        s[t] += v;
        __syncthreads();
    }
    if (idx < NN) g_off[idx] = s[t] - val;       // exclusive within block
    if (t == SCAN_B - 1) g_bsum[blockIdx.x] = s[t];
}

__global__ void k_scan_tot() {
    if (threadIdx.x == 0) {
        int run = 0;
        for (int b = 0; b < SCAN_NBLK; b++) {
            int v = g_bsum[b];
            g_bsum[b] = run;
            run += v;
        }
        g_off[NN] = run;   // == EE
    }
}

__global__ void k_scan_add() {
    int idx = blockIdx.x * SCAN_B + threadIdx.x;
    if (idx < NN) {
        int o = g_off[idx] + g_bsum[blockIdx.x];
        g_off[idx] = o;
        g_epos[idx] = o;
    }
}

__global__ void k_scatter(const int* __restrict__ edge_index,
                          const int* __restrict__ edge_attr) {
    int e = blockIdx.x * blockDim.x + threadIdx.x;
    if (e >= EE) return;
    int src = edge_index[e];
    int dst = edge_index[EE + e];
    int a0 = edge_attr[e * 3 + 0];
    int a1 = edge_attr[e * 3 + 1];
    int a2 = edge_attr[e * 3 + 2];
    int pos = atomicAdd(&g_epos[dst], 1);
    g_esrc[pos] = src;
    g_eattr[pos] = a0 | (a1 << 3) | (a2 << 6);
}

// ---------------------------------------------------------------------------
// Aggregation: one warp per node. g_aggr[n] = x[n] + sum_e relu(x[src]+emb)
__global__ void __launch_bounds__(256)
k_aggr(const float* __restrict__ bond_layer /* [3][8][D] */) {
    int n = blockIdx.x * (blockDim.x >> 5) + (threadIdx.x >> 5);
    int lane = threadIdx.x & 31;
    if (n >= NN) return;
    int beg = g_off[n];
    int end = g_off[n + 1];
    const float4* b4 = reinterpret_cast<const float4*>(bond_layer);
    const float4* xc = reinterpret_cast<const float4*>(g_xcur);
    float4 acc = xc[(long long)n * 32 + lane];
    #pragma unroll 2
    for (int e = beg; e < end; e++) {
        int src = g_esrc[e];
        int p = g_eattr[e];
        float4 e0 = b4[(p & 7) * 32 + lane];
        float4 e1 = b4[(8 + ((p >> 3) & 7)) * 32 + lane];
        float4 e2 = b4[(16 + ((p >> 6) & 7)) * 32 + lane];
        float4 xv = xc[(long long)src * 32 + lane];
        acc.x += fmaxf(xv.x + e0.x + e1.x + e2.x, 0.f);
        acc.y += fmaxf(xv.y + e0.y + e1.y + e2.y, 0.f);
        acc.z += fmaxf(xv.z + e0.z + e1.z + e2.z, 0.f);
        acc.w += fmaxf(xv.w + e0.w + e1.w + e2.w, 0.f);
    }
    reinterpret_cast<float4*>(g_aggr)[(long long)n * 32 + lane] = acc;
}

// ---------------------------------------------------------------------------
// Tensor-core GEMM (tf32) + bias + BN + relu.
// MODE 0: in = g_aggr (already x+aggr), out = g_h1
// MODE 1: in = g_h1, out = g_xcur, pool into g_pooled[pool_slot]
#define SA_STRIDE 132
#define SW_STRIDE 136

template <int MODE>
__global__ void __launch_bounds__(256, 1)
k_gemm_tc(const float* __restrict__ W, const float* __restrict__ bias,
          const float* __restrict__ gamma, const float* __restrict__ beta,
          const float* __restrict__ mean, const float* __restrict__ var,
          const int* __restrict__ batch, int pool_slot) {
    extern __shared__ uint32_t smem_u[];
    uint32_t* sA = smem_u;                 // [128][132]
    uint32_t* sW = sA + DD * SA_STRIDE;    // [128][136]

    const int tid = threadIdx.x;
    const int m0 = blockIdx.x * 128;

    // ---- Load A tile, convert to tf32 ----
    {
        const float4* Ag = reinterpret_cast<const float4*>(MODE == 0 ? g_aggr : g_h1);
        #pragma unroll
        for (int i = 0; i < 16; i++) {
            int idx = tid + i * 256;
            int row = idx >> 5;
            int c4  = idx & 31;
            int m = m0 + row;
            float4 v = make_float4(0.f, 0.f, 0.f, 0.f);
            if (m < NN) v = Ag[(long long)m * 32 + c4];
            uint4 tv;
            tv.x = f2tf32(v.x); tv.y = f2tf32(v.y); tv.z = f2tf32(v.z); tv.w = f2tf32(v.w);
            *reinterpret_cast<uint4*>(&sA[row * SA_STRIDE + c4 * 4]) = tv;
        }
    }
    // ---- Load W tile (tf32) ----
    {
        const float4* Wg = reinterpret_cast<const float4*>(W);
        #pragma unroll
        for (int i = 0; i < 16; i++) {
            int idx = tid + i * 256;
            int row = idx >> 5;
            int c4  = idx & 31;
            float4 w = Wg[row * 32 + c4];
            uint4 hv;
            hv.x = f2tf32(w.x); hv.y = f2tf32(w.y); hv.z = f2tf32(w.z); hv.w = f2tf32(w.w);
            *reinterpret_cast<uint4*>(&sW[row * SW_STRIDE + c4 * 4]) = hv;
        }
    }
    __syncthreads();

    const int w    = tid >> 5;
    const int lane = tid & 31;
    const int wm   = w & 3;
    const int wn   = w >> 2;
    const int gid  = lane >> 2;
    const int tig  = lane & 3;

    float acc[2][8][4];
    #pragma unroll
    for (int mi = 0; mi < 2; mi++)
        #pragma unroll
        for (int ni = 0; ni < 8; ni++)
            #pragma unroll
            for (int r = 0; r < 4; r++) acc[mi][ni][r] = 0.f;

    const uint32_t* aRow0  = sA + (wm * 32 + 0 * 16 + gid) * SA_STRIDE;
    const uint32_t* aRow0b = aRow0 + 8 * SA_STRIDE;
    const uint32_t* aRow1  = sA + (wm * 32 + 1 * 16 + gid) * SA_STRIDE;
    const uint32_t* aRow1b = aRow1 + 8 * SA_STRIDE;
    const int colbase = wn * 64 + gid;

    for (int kk = 0; kk < 16; kk++) {
        int k0 = kk * 8 + tig;
        uint32_t a0[4], a1[4];
        a0[0] = aRow0[k0];  a0[1] = aRow0b[k0];  a0[2] = aRow0[k0 + 4];  a0[3] = aRow0b[k0 + 4];
        a1[0] = aRow1[k0];  a1[1] = aRow1b[k0];  a1[2] = aRow1[k0 + 4];  a1[3] = aRow1b[k0 + 4];
        int kb0 = k0 * SW_STRIDE;
        int kb1 = (k0 + 4) * SW_STRIDE;
        #pragma unroll
        for (int ni = 0; ni < 8; ni++) {
            int c = colbase + ni * 8;
            uint32_t b0 = sW[kb0 + c], b1 = sW[kb1 + c];
            mma_tf32(acc[0][ni], a0, b0, b1);
            mma_tf32(acc[1][ni], a1, b0, b1);
        }
    }

    float* Cout = (MODE == 0) ? g_h1 : g_xcur;
    #pragma unroll
    for (int ni = 0; ni < 8; ni++) {
        int c = wn * 64 + ni * 8 + tig * 2;
        float2 bi = *reinterpret_cast<const float2*>(bias + c);
        float2 ga = *reinterpret_cast<const float2*>(gamma + c);
        float2 be = *reinterpret_cast<const float2*>(beta + c);
        float2 me = *reinterpret_cast<const float2*>(mean + c);
        float2 va = *reinterpret_cast<const float2*>(var + c);
        float scx = ga.x * rsqrtf(va.x + BN_EPS);
        float scy = ga.y * rsqrtf(va.y + BN_EPS);
        float shx = be.x - me.x * scx;
        float shy = be.y - me.y * scy;
        #pragma unroll
        for (int mi = 0; mi < 2; mi++) {
            #pragma unroll
            for (int h = 0; h < 2; h++) {
                int row = m0 + wm * 32 + mi * 16 + gid + h * 8;
                if (row < NN) {
                    float v0 = acc[mi][ni][h * 2 + 0];
                    float v1 = acc[mi][ni][h * 2 + 1];
                    float r0 = fmaxf((v0 + bi.x) * scx + shx, 0.f);
                    float r1 = fmaxf((v1 + bi.y) * scy + shy, 0.f);
                    *reinterpret_cast<float2*>(&Cout[(long long)row * DD + c]) = make_float2(r0, r1);
                    if (MODE == 1) {
                        int g = batch[row];
                        red_v2(&g_pooled[pool_slot * GG * DD + g * DD + c], r0, r1);
                    }
                }
            }
        }
    }
}

// ---------------------------------------------------------------------------
__global__ void k_head(const float* __restrict__ fc_w, const float* __restrict__ fc_b,
                       float* __restrict__ out) {
    __shared__ float sp[(LL + 1) * DD];
    int g = blockIdx.x;
    float inv = 1.0f / fmaxf(g_counts[g], 1.0f);
    for (int i = threadIdx.x; i < (LL + 1) * DD; i += blockDim.x) {
        int l = i >> 7;
        int d = i & 127;
        sp[i] = g_pooled[l * GG * DD + g * DD + d] * inv;
    }
    __syncthreads();
    int o = threadIdx.x;
    if (o < OO) {
        float s = 0.f;
        #pragma unroll
        for (int l = 0; l < LL + 1; l++) {
            float partial = 0.f;
            for (int d = 0; d < DD; d++) {
                partial += sp[l * DD + d] * fc_w[(l * DD + d) * OO + o];
            }
            s += partial + fc_b[l * OO + o];
        }
        out[g * OO + o] = s;
    }
}

// ---------------------------------------------------------------------------
extern "C" void kernel_launch(void* const* d_in, const int* in_sizes, int n_in,
                              void* d_out, int out_size) {
    const float* x          = (const float*)d_in[0];
    const int*   edge_index = (const int*)d_in[1];
    const int*   edge_attr  = (const int*)d_in[2];
    const int*   batch      = (const int*)d_in[3];
    const float* bond_emb   = (const float*)d_in[4];
    const float* conv_w1    = (const float*)d_in[5];
    const float* conv_b1    = (const float*)d_in[6];
    const float* cbn_g      = (const float*)d_in[7];
    const float* cbn_b      = (const float*)d_in[8];
    const float* cbn_m      = (const float*)d_in[9];
    const float* cbn_v      = (const float*)d_in[10];
    const float* conv_w2    = (const float*)d_in[11];
    const float* conv_b2    = (const float*)d_in[12];
    const float* bn_g       = (const float*)d_in[13];
    const float* bn_b       = (const float*)d_in[14];
    const float* bn_m       = (const float*)d_in[15];
    const float* bn_v       = (const float*)d_in[16];
    const float* fc_w       = (const float*)d_in[17];
    const float* fc_b       = (const float*)d_in[18];
    float* out = (float*)d_out;

    const int smem_bytes = (DD * SA_STRIDE + DD * SW_STRIDE) * sizeof(uint32_t); // 134 KB
    static bool attr_done = false;
    if (!attr_done) {
        cudaFuncSetAttribute(k_gemm_tc<0>, cudaFuncAttributeMaxDynamicSharedMemorySize, smem_bytes);
        cudaFuncSetAttribute(k_gemm_tc<1>, cudaFuncAttributeMaxDynamicSharedMemorySize, smem_bytes);
        attr_done = true;
    }

    // Prologue: zero, counts, x copy + pool0, CSR build
    k_zero_meta<<<512, 256>>>();
    k_counts<<<(NN + 255) / 256, 256>>>(batch);
    {
        long long tot = (long long)NN * 32;
        k_copy_pool0<<<(int)((tot + 255) / 256), 256>>>(x, batch);
    }
    k_hist<<<(EE + 255) / 256, 256>>>(edge_index);
    k_scan_part<<<SCAN_NBLK, SCAN_B>>>();
    k_scan_tot<<<1, 32>>>();
    k_scan_add<<<SCAN_NBLK, SCAN_B>>>();
    k_scatter<<<(EE + 255) / 256, 256>>>(edge_index, edge_attr);

    const int gemm_grid = (NN + 127) / 128;
    const int aggr_grid = (NN + 7) / 8;   // 8 warps (nodes) per 256-thread block

    for (int i = 0; i < LL; i++) {
        k_aggr<<<aggr_grid, 256>>>(bond_emb + (long long)i * 3 * 8 * DD);
        k_gemm_tc<0><<<gemm_grid, 256, smem_bytes>>>(
            conv_w1 + (long long)i * DD * DD, conv_b1 + i * DD,
            cbn_g + i * DD, cbn_b + i * DD, cbn_m + i * DD, cbn_v + i * DD,
            batch, 0);
        k_gemm_tc<1><<<gemm_grid, 256, smem_bytes>>>(
            conv_w2 + (long long)i * DD * DD, conv_b2 + i * DD,
            bn_g + i * DD, bn_b + i * DD, bn_m + i * DD, bn_v + i * DD,
            batch, i + 1);
    }

    k_head<<<GG, 128>>>(fc_w, fc_b, out);
    (void)in_sizes; (void)n_in; (void)out_size;
}